// round 2
// baseline (speedup 1.0000x reference)
#include <cuda_runtime.h>
#include <cstdint>

#define N_NODES 50000
#define N_EDGES 800000
#define F_IN    256
#define H_DIM   256
#define L_DIM   128
#define EPS_BN  1e-5f

// ---------------- scratch (device globals; no allocations allowed) ----------
__device__ float  g_h1[(size_t)N_NODES * H_DIM];
__device__ float  g_h2[(size_t)N_NODES * H_DIM];
__device__ int    g_cnt[N_NODES + 1];
__device__ int    g_rowptr[N_NODES + 1];
__device__ int    g_ofs[N_NODES];
__device__ int    g_scols[N_EDGES];
__device__ float  g_svals[N_EDGES];
__device__ double g_stats[2 * H_DIM];   // [0..H): sum, [H..2H): sumsq
__device__ float  g_a[H_DIM];
__device__ float  g_c[H_DIM];

// ---------------- CSR build --------------------------------------------------
__global__ void hist_kernel(const int* __restrict__ rows, int E) {
    int i = blockIdx.x * blockDim.x + threadIdx.x;
    if (i < E) atomicAdd(&g_cnt[rows[i]], 1);
}

__global__ void scan_kernel() {
    __shared__ int part[1024];
    const int t = threadIdx.x;
    const int CH = (N_NODES + 1023) / 1024;
    const int base = t * CH;
    int local = 0;
    for (int i = 0; i < CH; i++) {
        int r = base + i;
        if (r < N_NODES) local += g_cnt[r];
    }
    part[t] = local;
    __syncthreads();
    for (int off = 1; off < 1024; off <<= 1) {
        int v = (t >= off) ? part[t - off] : 0;
        __syncthreads();
        part[t] += v;
        __syncthreads();
    }
    int incl = part[t];
    int run = incl - local;   // exclusive prefix
    for (int i = 0; i < CH; i++) {
        int r = base + i;
        if (r < N_NODES) {
            g_rowptr[r] = run;
            g_ofs[r]    = run;
            run += g_cnt[r];
        }
    }
    if (t == 1023) g_rowptr[N_NODES] = incl;
}

__global__ void scatter_kernel(const int* __restrict__ rows,
                               const int* __restrict__ cols,
                               const float* __restrict__ vals, int E) {
    int i = blockIdx.x * blockDim.x + threadIdx.x;
    if (i < E) {
        int p = atomicAdd(&g_ofs[rows[i]], 1);
        g_scols[p] = cols[i];
        g_svals[p] = vals[i];
    }
}

// ---------------- SpMM: y[row][t] = sum_e svals[e] * x[scols[e]][t] ----------
__global__ void spmm_kernel(const float* __restrict__ x, float* __restrict__ y) {
    const int row = blockIdx.x;
    const int t = threadIdx.x;                 // 256 = H_DIM
    const int s = g_rowptr[row], e = g_rowptr[row + 1];
    float acc = 0.f;
    for (int p = s; p < e; p++) {
        int   c = __ldg(&g_scols[p]);
        float v = __ldg(&g_svals[p]);
        acc += v * __ldg(&x[(size_t)c * H_DIM + t]);
    }
    y[(size_t)row * H_DIM + t] = acc;
}

// ---------------- BN ---------------------------------------------------------
#define BN_ROWS_PB 128
__global__ void bn_stats_kernel(const float* __restrict__ x, int M) {
    const int t = threadIdx.x;                 // channel
    const int r0 = blockIdx.x * BN_ROWS_PB;
    float s = 0.f, sq = 0.f;
    #pragma unroll 4
    for (int i = 0; i < BN_ROWS_PB; i++) {
        int r = r0 + i;
        if (r < M) {
            float v = x[(size_t)r * H_DIM + t];
            s += v; sq += v * v;
        }
    }
    atomicAdd(&g_stats[t], (double)s);
    atomicAdd(&g_stats[H_DIM + t], (double)sq);
}

__global__ void bn_final_kernel(const float* __restrict__ gamma,
                                const float* __restrict__ beta, int M) {
    const int t = threadIdx.x;
    double s = g_stats[t], sq = g_stats[H_DIM + t];
    float mean = (float)(s / M);
    float var  = (float)(sq / M) - mean * mean;
    float rstd = rsqrtf(var + EPS_BN);
    float a = gamma[t] * rstd;
    g_a[t] = a;
    g_c[t] = beta[t] - mean * a;
}

__global__ void bn_apply_kernel(const float* __restrict__ x, float* __restrict__ y, int M) {
    const int idx = blockIdx.x * blockDim.x + threadIdx.x;   // float4 index
    const int total4 = M * (H_DIM / 4);
    if (idx >= total4) return;
    const int col4 = idx & (H_DIM / 4 - 1);
    float4 v = reinterpret_cast<const float4*>(x)[idx];
    float4 a = reinterpret_cast<const float4*>(g_a)[col4];
    float4 c = reinterpret_cast<const float4*>(g_c)[col4];
    v.x = fmaxf(v.x * a.x + c.x, 0.f);
    v.y = fmaxf(v.y * a.y + c.y, 0.f);
    v.z = fmaxf(v.z * a.z + c.z, 0.f);
    v.w = fmaxf(v.w * a.w + c.w, 0.f);
    reinterpret_cast<float4*>(y)[idx] = v;
}

// ---------------- SGEMM: C[M,Nc] = A[M,K] @ B[K,Nc] (+bias), optional gather -
template<bool GATHER>
__global__ __launch_bounds__(256, 2)
void sgemm_kernel(const float* __restrict__ A, const float* __restrict__ B,
                  const float* __restrict__ bias, float* __restrict__ C,
                  int M, int K, int Nc, const int* __restrict__ gidx) {
    const int BM = 128, BN = 128, BK = 16;
    __shared__ float As[BK][BM + 4];
    __shared__ float Bs[BK][BN + 4];

    const int tid = threadIdx.x;
    const int tx = tid & 15, ty = tid >> 4;
    const int row0 = blockIdx.y * BM, col0 = blockIdx.x * BN;

    // A loader: 128 rows x 16 k = 512 float4 -> 2 per thread
    const int a_r  = tid >> 2;        // 0..63
    const int a_k4 = (tid & 3) * 4;   // k offset within BK
    // B loader: 16 rows x 128 cols = 512 float4 -> 2 per thread
    const int b_r  = tid >> 5;        // 0..7
    const int b_c  = (tid & 31) * 4;

    float acc[8][8] = {};

    for (int k0 = 0; k0 < K; k0 += BK) {
        #pragma unroll
        for (int p = 0; p < 2; p++) {
            int m = a_r + p * 64;
            int gm = row0 + m;
            float4 v = make_float4(0.f, 0.f, 0.f, 0.f);
            if (gm < M) {
                int src = GATHER ? __ldg(&gidx[gm]) : gm;
                v = *reinterpret_cast<const float4*>(A + (size_t)src * K + k0 + a_k4);
            }
            As[a_k4 + 0][m] = v.x;
            As[a_k4 + 1][m] = v.y;
            As[a_k4 + 2][m] = v.z;
            As[a_k4 + 3][m] = v.w;
        }
        #pragma unroll
        for (int p = 0; p < 2; p++) {
            int kk = b_r + p * 8;
            float4 v = *reinterpret_cast<const float4*>(B + (size_t)(k0 + kk) * Nc + col0 + b_c);
            *reinterpret_cast<float4*>(&Bs[kk][b_c]) = v;
        }
        __syncthreads();

        #pragma unroll
        for (int kk = 0; kk < BK; kk++) {
            float ar[8], br[8];
            float4 a0 = *reinterpret_cast<const float4*>(&As[kk][ty * 8]);
            float4 a1 = *reinterpret_cast<const float4*>(&As[kk][ty * 8 + 4]);
            float4 b0 = *reinterpret_cast<const float4*>(&Bs[kk][tx * 8]);
            float4 b1 = *reinterpret_cast<const float4*>(&Bs[kk][tx * 8 + 4]);
            ar[0]=a0.x; ar[1]=a0.y; ar[2]=a0.z; ar[3]=a0.w;
            ar[4]=a1.x; ar[5]=a1.y; ar[6]=a1.z; ar[7]=a1.w;
            br[0]=b0.x; br[1]=b0.y; br[2]=b0.z; br[3]=b0.w;
            br[4]=b1.x; br[5]=b1.y; br[6]=b1.z; br[7]=b1.w;
            #pragma unroll
            for (int i = 0; i < 8; i++)
                #pragma unroll
                for (int j = 0; j < 8; j++)
                    acc[i][j] += ar[i] * br[j];
        }
        __syncthreads();
    }

    #pragma unroll
    for (int i = 0; i < 8; i++) {
        int gm = row0 + ty * 8 + i;
        if (gm >= M) continue;
        #pragma unroll
        for (int j = 0; j < 8; j += 4) {
            int gn = col0 + tx * 8 + j;
            float4 v;
            v.x = acc[i][j];   v.y = acc[i][j+1];
            v.z = acc[i][j+2]; v.w = acc[i][j+3];
            if (bias) {
                v.x += __ldg(&bias[gn]);   v.y += __ldg(&bias[gn+1]);
                v.z += __ldg(&bias[gn+2]); v.w += __ldg(&bias[gn+3]);
            }
            *reinterpret_cast<float4*>(C + (size_t)gm * Nc + gn) = v;
        }
    }
}

// ---------------- launch -----------------------------------------------------
extern "C" void kernel_launch(void* const* d_in, const int* in_sizes, int n_in,
                              void* d_out, int out_size) {
    const float* features  = (const float*)d_in[0];
    const float* edge_vals = (const float*)d_in[1];
    const float* W1        = (const float*)d_in[2];
    const float* db1       = (const float*)d_in[3];
    // d_in[4] = b1  (cancels inside BatchNorm, skipped)
    const float* g1        = (const float*)d_in[5];
    const float* be1       = (const float*)d_in[6];
    const float* W2        = (const float*)d_in[7];
    // d_in[8] = b2  (cancels inside BatchNorm, skipped)
    const float* g2        = (const float*)d_in[9];
    const float* be2       = (const float*)d_in[10];
    const float* Wf        = (const float*)d_in[11];
    const float* bf        = (const float*)d_in[12];
    const int*   edge_rows = (const int*)d_in[13];
    const int*   edge_cols = (const int*)d_in[14];
    const int*   idx       = (const int*)d_in[15];

    const int E  = in_sizes[1];
    const int Mi = in_sizes[15];          // number of gathered output rows
    float* out = (float*)d_out;

    float *h1, *h2; int *cnt;
    cudaGetSymbolAddress((void**)&h1,  g_h1);
    cudaGetSymbolAddress((void**)&h2,  g_h2);
    cudaGetSymbolAddress((void**)&cnt, g_cnt);
    double* stats;
    cudaGetSymbolAddress((void**)&stats, g_stats);

    // --- CSR build (per launch; cheap) ---
    cudaMemsetAsync(cnt, 0, (N_NODES + 1) * sizeof(int), 0);
    hist_kernel<<<(E + 255) / 256, 256>>>(edge_rows, E);
    scan_kernel<<<1, 1024>>>();
    scatter_kernel<<<(E + 255) / 256, 256>>>(edge_rows, edge_cols, edge_vals, E);

    const dim3 gemm_grid(H_DIM / 128, (N_NODES + 127) / 128);
    const int  bn_blocks  = (N_NODES + BN_ROWS_PB - 1) / BN_ROWS_PB;
    const int  app_total4 = N_NODES * (H_DIM / 4);
    const int  app_blocks = (app_total4 + 255) / 256;

    // --- layer 1 ---
    sgemm_kernel<false><<<gemm_grid, 256>>>(features, W1, db1, h1,
                                            N_NODES, F_IN, H_DIM, nullptr);
    spmm_kernel<<<N_NODES, H_DIM>>>(h1, h2);
    cudaMemsetAsync(stats, 0, 2 * H_DIM * sizeof(double), 0);
    bn_stats_kernel<<<bn_blocks, H_DIM>>>(h2, N_NODES);
    bn_final_kernel<<<1, H_DIM>>>(g1, be1, N_NODES);
    bn_apply_kernel<<<app_blocks, 256>>>(h2, h1, N_NODES);

    // --- layer 2 ---
    sgemm_kernel<false><<<gemm_grid, 256>>>(h1, W2, nullptr, h2,
                                            N_NODES, H_DIM, H_DIM, nullptr);
    spmm_kernel<<<N_NODES, H_DIM>>>(h2, h1);
    cudaMemsetAsync(stats, 0, 2 * H_DIM * sizeof(double), 0);
    bn_stats_kernel<<<bn_blocks, H_DIM>>>(h1, N_NODES);
    bn_final_kernel<<<1, H_DIM>>>(g2, be2, N_NODES);
    bn_apply_kernel<<<app_blocks, 256>>>(h1, h2, N_NODES);

    // --- head: gathered rows only ---
    const dim3 head_grid(L_DIM / 128, (Mi + 127) / 128);
    sgemm_kernel<true><<<head_grid, 256>>>(h2, Wf, bf, out,
                                           Mi, H_DIM, L_DIM, idx);
}

// round 3
// speedup vs baseline: 1.9426x; 1.9426x over previous
#include <cuda_runtime.h>
#include <cstdint>

#define N_NODES 50000
#define N_EDGES 800000
#define F_IN    256
#define H_DIM   256
#define L_DIM   128
#define EPS_BN  1e-5f

// ---------------- scratch (device globals; no allocations allowed) ----------
__device__ float  g_h1[(size_t)N_NODES * H_DIM];
__device__ float  g_h2[(size_t)N_NODES * H_DIM];
__device__ int    g_cnt[N_NODES + 1];
__device__ int    g_rowptr[N_NODES + 1];
__device__ int    g_ofs[N_NODES];
__device__ int    g_scols[N_EDGES];
__device__ float  g_svals[N_EDGES];
__device__ double g_stats[2 * H_DIM];   // [0..H): sum, [H..2H): sumsq
__device__ float  g_a1[H_DIM];
__device__ float  g_c1[H_DIM];
__device__ float  g_a2[H_DIM];
__device__ float  g_c2[H_DIM];

// ---------------- helpers ----------------------------------------------------
__device__ __forceinline__ float f2tf(float x) {
    uint32_t u;
    asm("cvt.rna.tf32.f32 %0, %1;" : "=r"(u) : "f"(x));
    return __uint_as_float(u);
}

__device__ __forceinline__ void mma_tf32(float* c, const uint32_t* a, const uint32_t* b) {
    asm volatile(
        "mma.sync.aligned.m16n8k8.row.col.f32.tf32.tf32.f32 "
        "{%0,%1,%2,%3}, {%4,%5,%6,%7}, {%8,%9}, {%0,%1,%2,%3};"
        : "+f"(c[0]), "+f"(c[1]), "+f"(c[2]), "+f"(c[3])
        : "r"(a[0]), "r"(a[1]), "r"(a[2]), "r"(a[3]), "r"(b[0]), "r"(b[1]));
}

// ---------------- CSR build --------------------------------------------------
__global__ void hist_kernel(const int* __restrict__ rows, int E) {
    int i = blockIdx.x * blockDim.x + threadIdx.x;
    if (i < E) atomicAdd(&g_cnt[rows[i]], 1);
}

__global__ void scan_kernel() {
    __shared__ int part[1024];
    const int t = threadIdx.x;
    const int CH = (N_NODES + 1023) / 1024;
    const int base = t * CH;
    int local = 0;
    for (int i = 0; i < CH; i++) {
        int r = base + i;
        if (r < N_NODES) local += g_cnt[r];
    }
    part[t] = local;
    __syncthreads();
    for (int off = 1; off < 1024; off <<= 1) {
        int v = (t >= off) ? part[t - off] : 0;
        __syncthreads();
        part[t] += v;
        __syncthreads();
    }
    int incl = part[t];
    int run = incl - local;   // exclusive prefix
    for (int i = 0; i < CH; i++) {
        int r = base + i;
        if (r < N_NODES) {
            g_rowptr[r] = run;
            g_ofs[r]    = run;
            run += g_cnt[r];
        }
    }
    if (t == 1023) g_rowptr[N_NODES] = incl;
}

__global__ void scatter_kernel(const int* __restrict__ rows,
                               const int* __restrict__ cols,
                               const float* __restrict__ vals, int E) {
    int i = blockIdx.x * blockDim.x + threadIdx.x;
    if (i < E) {
        int p = atomicAdd(&g_ofs[rows[i]], 1);
        g_scols[p] = cols[i];
        g_svals[p] = vals[i];
    }
}

// ---------------- SpMM: y[row][:] = sum_e v_e * x[col_e][:]  (float4) -------
__global__ void spmm_kernel(const float* __restrict__ x, float* __restrict__ y) {
    const int tid = threadIdx.x;
    const int row = blockIdx.x * 4 + (tid >> 6);
    const int c4  = tid & 63;
    if (row >= N_NODES) return;
    const int s = g_rowptr[row], e = g_rowptr[row + 1];
    float4 acc = make_float4(0.f, 0.f, 0.f, 0.f);
    for (int p = s; p < e; p++) {
        int   col = __ldg(&g_scols[p]);
        float v   = __ldg(&g_svals[p]);
        float4 xv = *reinterpret_cast<const float4*>(x + (size_t)col * H_DIM + c4 * 4);
        acc.x += v * xv.x; acc.y += v * xv.y;
        acc.z += v * xv.z; acc.w += v * xv.w;
    }
    *reinterpret_cast<float4*>(y + (size_t)row * H_DIM + c4 * 4) = acc;
}

// ---------------- BN stats ---------------------------------------------------
#define BN_ROWS_PB 128
__global__ void bn_stats_kernel(const float* __restrict__ x, int M) {
    const int t = threadIdx.x;                 // channel
    const int r0 = blockIdx.x * BN_ROWS_PB;
    float s = 0.f, sq = 0.f;
    #pragma unroll 4
    for (int i = 0; i < BN_ROWS_PB; i++) {
        int r = r0 + i;
        if (r < M) {
            float v = x[(size_t)r * H_DIM + t];
            s += v; sq += v * v;
        }
    }
    atomicAdd(&g_stats[t], (double)s);
    atomicAdd(&g_stats[H_DIM + t], (double)sq);
}

__global__ void bn_final_kernel(const float* __restrict__ gamma,
                                const float* __restrict__ beta,
                                float* __restrict__ oa, float* __restrict__ oc, int M) {
    const int t = threadIdx.x;
    double s = g_stats[t], sq = g_stats[H_DIM + t];
    float mean = (float)(s / M);
    float var  = (float)(sq / M) - mean * mean;
    float rstd = rsqrtf(var + EPS_BN);
    float a = gamma[t] * rstd;
    oa[t] = a;
    oc[t] = beta[t] - mean * a;
}

// ---------------- tf32 tensor-core GEMM -------------------------------------
// C[M,Nc] = op(A)[M,K] @ B[K,Nc] (+bias)
//   FUSE_BN: A element at channel k transformed relu(x*bna[k]+bnc[k]) on load
//   GATHER : A row m read from A[gidx[m]]
// Block tile 128x128, BK=16, 256 threads = 8 warps (2x4), warp tile 64x32.
template<bool FUSE_BN, bool GATHER, bool BIAS>
__global__ __launch_bounds__(256)
void tf32_gemm(const float* __restrict__ A, const float* __restrict__ B,
               const float* __restrict__ bias, float* __restrict__ C,
               int M, int K, int Nc, const int* __restrict__ gidx,
               const float* __restrict__ bna, const float* __restrict__ bnc) {
    __shared__ float As[2][128][20];   // [m][k], stride 20 -> conflict-free frags
    __shared__ float Bs[2][16][136];   // [k][n], stride 136 -> conflict-free frags

    const int tid  = threadIdx.x;
    const int lane = tid & 31;
    const int g    = lane >> 2;        // group id 0..7
    const int t4   = lane & 3;         // thread in group
    const int wid  = tid >> 5;
    const int wm   = wid & 1;          // warp m (0..1) -> 64 rows
    const int wn   = wid >> 1;         // warp n (0..3) -> 32 cols
    const int row0 = blockIdx.y * 128;
    const int col0 = blockIdx.x * 128;

    // A loader: rows {ar, ar+64}, 4 k-values at ac
    const int ar = tid >> 2;
    const int ac = (tid & 3) * 4;
    // B loader: k rows {br, br+8}, 4 n-values at bc
    const int br = tid >> 5;
    const int bc = (tid & 31) * 4;

    float4 av[2], bv[2];

    auto load_tile = [&](int k0) {
        #pragma unroll
        for (int p = 0; p < 2; p++) {
            int gm = row0 + ar + p * 64;
            float4 v = make_float4(0.f, 0.f, 0.f, 0.f);
            if (gm < M) {
                int src = GATHER ? __ldg(&gidx[gm]) : gm;
                v = *reinterpret_cast<const float4*>(A + (size_t)src * K + k0 + ac);
            }
            if (FUSE_BN) {
                float4 a4 = *reinterpret_cast<const float4*>(bna + k0 + ac);
                float4 c4 = *reinterpret_cast<const float4*>(bnc + k0 + ac);
                v.x = fmaxf(v.x * a4.x + c4.x, 0.f);
                v.y = fmaxf(v.y * a4.y + c4.y, 0.f);
                v.z = fmaxf(v.z * a4.z + c4.z, 0.f);
                v.w = fmaxf(v.w * a4.w + c4.w, 0.f);
            }
            av[p] = v;
        }
        #pragma unroll
        for (int p = 0; p < 2; p++) {
            bv[p] = *reinterpret_cast<const float4*>(B + (size_t)(k0 + br + p * 8) * Nc + col0 + bc);
        }
    };

    auto store_tile = [&](int buf) {
        #pragma unroll
        for (int p = 0; p < 2; p++) {
            int m = ar + p * 64;
            As[buf][m][ac + 0] = f2tf(av[p].x);
            As[buf][m][ac + 1] = f2tf(av[p].y);
            As[buf][m][ac + 2] = f2tf(av[p].z);
            As[buf][m][ac + 3] = f2tf(av[p].w);
        }
        #pragma unroll
        for (int p = 0; p < 2; p++) {
            int kk = br + p * 8;
            Bs[buf][kk][bc + 0] = f2tf(bv[p].x);
            Bs[buf][kk][bc + 1] = f2tf(bv[p].y);
            Bs[buf][kk][bc + 2] = f2tf(bv[p].z);
            Bs[buf][kk][bc + 3] = f2tf(bv[p].w);
        }
    };

    float acc[4][4][4] = {};

    const int KT = K / 16;
    load_tile(0);
    store_tile(0);
    __syncthreads();
    int buf = 0;

    for (int kt = 0; kt < KT; kt++) {
        if (kt + 1 < KT) load_tile((kt + 1) * 16);

        #pragma unroll
        for (int kk = 0; kk < 16; kk += 8) {
            uint32_t af[4][4], bfr[4][2];
            #pragma unroll
            for (int mf = 0; mf < 4; mf++) {
                int m = wm * 64 + mf * 16;
                af[mf][0] = __float_as_uint(As[buf][m + g    ][kk + t4    ]);
                af[mf][1] = __float_as_uint(As[buf][m + g + 8][kk + t4    ]);
                af[mf][2] = __float_as_uint(As[buf][m + g    ][kk + t4 + 4]);
                af[mf][3] = __float_as_uint(As[buf][m + g + 8][kk + t4 + 4]);
            }
            #pragma unroll
            for (int nf = 0; nf < 4; nf++) {
                int n = wn * 32 + nf * 8;
                bfr[nf][0] = __float_as_uint(Bs[buf][kk + t4    ][n + g]);
                bfr[nf][1] = __float_as_uint(Bs[buf][kk + t4 + 4][n + g]);
            }
            #pragma unroll
            for (int mf = 0; mf < 4; mf++)
                #pragma unroll
                for (int nf = 0; nf < 4; nf++)
                    mma_tf32(acc[mf][nf], af[mf], bfr[nf]);
        }

        if (kt + 1 < KT) {
            store_tile(buf ^ 1);
            __syncthreads();
            buf ^= 1;
        }
    }

    // epilogue
    #pragma unroll
    for (int mf = 0; mf < 4; mf++) {
        #pragma unroll
        for (int nf = 0; nf < 4; nf++) {
            int rr = row0 + wm * 64 + mf * 16 + g;
            int cc = col0 + wn * 32 + nf * 8 + t4 * 2;
            float b0 = 0.f, b1 = 0.f;
            if (BIAS) { b0 = __ldg(&bias[cc]); b1 = __ldg(&bias[cc + 1]); }
            if (rr < M) {
                float2 v = make_float2(acc[mf][nf][0] + b0, acc[mf][nf][1] + b1);
                *reinterpret_cast<float2*>(C + (size_t)rr * Nc + cc) = v;
            }
            if (rr + 8 < M) {
                float2 v = make_float2(acc[mf][nf][2] + b0, acc[mf][nf][3] + b1);
                *reinterpret_cast<float2*>(C + (size_t)(rr + 8) * Nc + cc) = v;
            }
        }
    }
}

// ---------------- launch -----------------------------------------------------
extern "C" void kernel_launch(void* const* d_in, const int* in_sizes, int n_in,
                              void* d_out, int out_size) {
    const float* features  = (const float*)d_in[0];
    const float* edge_vals = (const float*)d_in[1];
    const float* W1        = (const float*)d_in[2];
    const float* db1       = (const float*)d_in[3];
    // d_in[4] = b1  (cancels inside BatchNorm, skipped)
    const float* g1        = (const float*)d_in[5];
    const float* be1       = (const float*)d_in[6];
    const float* W2        = (const float*)d_in[7];
    // d_in[8] = b2  (cancels inside BatchNorm, skipped)
    const float* g2        = (const float*)d_in[9];
    const float* be2       = (const float*)d_in[10];
    const float* Wf        = (const float*)d_in[11];
    const float* bf        = (const float*)d_in[12];
    const int*   edge_rows = (const int*)d_in[13];
    const int*   edge_cols = (const int*)d_in[14];
    const int*   idx       = (const int*)d_in[15];

    const int E  = in_sizes[1];
    const int Mi = in_sizes[15];
    float* out = (float*)d_out;

    float *h1, *h2, *a1, *c1, *a2, *c2;
    int* cnt; double* stats;
    cudaGetSymbolAddress((void**)&h1,  g_h1);
    cudaGetSymbolAddress((void**)&h2,  g_h2);
    cudaGetSymbolAddress((void**)&cnt, g_cnt);
    cudaGetSymbolAddress((void**)&stats, g_stats);
    cudaGetSymbolAddress((void**)&a1, g_a1);
    cudaGetSymbolAddress((void**)&c1, g_c1);
    cudaGetSymbolAddress((void**)&a2, g_a2);
    cudaGetSymbolAddress((void**)&c2, g_c2);

    // --- CSR build ---
    cudaMemsetAsync(cnt, 0, (N_NODES + 1) * sizeof(int), 0);
    hist_kernel<<<(E + 255) / 256, 256>>>(edge_rows, E);
    scan_kernel<<<1, 1024>>>();
    scatter_kernel<<<(E + 255) / 256, 256>>>(edge_rows, edge_cols, edge_vals, E);

    const dim3 gemm_grid(H_DIM / 128, (N_NODES + 127) / 128);
    const int  bn_blocks   = (N_NODES + BN_ROWS_PB - 1) / BN_ROWS_PB;
    const int  spmm_blocks = (N_NODES + 3) / 4;

    // --- layer 1: h1 = features @ W1 + db1 ---
    tf32_gemm<false, false, true><<<gemm_grid, 256>>>(
        features, W1, db1, h1, N_NODES, F_IN, H_DIM, nullptr, nullptr, nullptr);
    spmm_kernel<<<spmm_blocks, 256>>>(h1, h2);
    cudaMemsetAsync(stats, 0, 2 * H_DIM * sizeof(double), 0);
    bn_stats_kernel<<<bn_blocks, H_DIM>>>(h2, N_NODES);
    bn_final_kernel<<<1, H_DIM>>>(g1, be1, a1, c1, N_NODES);

    // --- layer 2: h1 = relu(bn1(h2)) @ W2  (BN fused into A load) ---
    tf32_gemm<true, false, false><<<gemm_grid, 256>>>(
        h2, W2, nullptr, h1, N_NODES, H_DIM, H_DIM, nullptr, a1, c1);
    spmm_kernel<<<spmm_blocks, 256>>>(h1, h2);
    cudaMemsetAsync(stats, 0, 2 * H_DIM * sizeof(double), 0);
    bn_stats_kernel<<<bn_blocks, H_DIM>>>(h2, N_NODES);
    bn_final_kernel<<<1, H_DIM>>>(g2, be2, a2, c2, N_NODES);

    // --- head: out = relu(bn2(h2))[idx] @ Wf + bf  (gather + BN fused) ---
    const dim3 head_grid(L_DIM / 128, (Mi + 127) / 128);
    tf32_gemm<true, true, true><<<head_grid, 256>>>(
        h2, Wf, bf, out, Mi, H_DIM, L_DIM, idx, a2, c2);
}

// round 8
// speedup vs baseline: 2.4442x; 1.2582x over previous
#include <cuda_runtime.h>
#include <cuda_fp16.h>
#include <cstdint>

#define N_NODES 50000
#define N_EDGES 800000
#define KDIM    256
#define H_DIM   256
#define L_DIM   128
#define EPS_BN  1e-5f

// ---------------- scratch (device globals; no allocations allowed) ----------
__device__ __align__(16) __half g_hH[(size_t)N_NODES * H_DIM];   // GEMM half outputs
__device__ __align__(16) float  g_yF[(size_t)N_NODES * H_DIM];   // SpMM fp32 outputs
__device__ __align__(16) __half g_W1h[KDIM * H_DIM];
__device__ __align__(16) __half g_W2h[KDIM * H_DIM];
__device__ __align__(16) __half g_Wfh[KDIM * L_DIM];
__device__ int    g_cnt[N_NODES + 1];
__device__ int    g_rowptr[N_NODES + 1];
__device__ int    g_ofs[N_NODES];
__device__ int    g_scols[N_EDGES];
__device__ float  g_svals[N_EDGES];
__device__ double g_stats[2 * H_DIM];
__device__ __align__(16) float g_a1[H_DIM];
__device__ __align__(16) float g_c1[H_DIM];
__device__ __align__(16) float g_a2[H_DIM];
__device__ __align__(16) float g_c2[H_DIM];

// ---------------- helpers ----------------------------------------------------
__device__ __forceinline__ uint32_t smem_u32(const void* p) {
    uint32_t a;
    asm("{ .reg .u64 t; cvta.to.shared.u64 t, %1; cvt.u32.u64 %0, t; }"
        : "=r"(a) : "l"(p));
    return a;
}

__device__ __forceinline__ uint32_t pack_h2(float a, float b) {
    __half2 h = __floats2half2_rn(a, b);
    return *reinterpret_cast<uint32_t*>(&h);
}

// ---------------- CSR build --------------------------------------------------
__global__ void hist_kernel(const int* __restrict__ rows, int E) {
    int i = blockIdx.x * blockDim.x + threadIdx.x;
    if (i < E) atomicAdd(&g_cnt[rows[i]], 1);
}

__global__ void scan_kernel() {
    __shared__ int part[1024];
    const int t = threadIdx.x;
    const int CH = (N_NODES + 1023) / 1024;
    const int base = t * CH;
    int local = 0;
    for (int i = 0; i < CH; i++) {
        int r = base + i;
        if (r < N_NODES) local += g_cnt[r];
    }
    part[t] = local;
    __syncthreads();
    for (int off = 1; off < 1024; off <<= 1) {
        int v = (t >= off) ? part[t - off] : 0;
        __syncthreads();
        part[t] += v;
        __syncthreads();
    }
    int incl = part[t];
    int run = incl - local;
    for (int i = 0; i < CH; i++) {
        int r = base + i;
        if (r < N_NODES) {
            g_rowptr[r] = run;
            g_ofs[r]    = run;
            run += g_cnt[r];
        }
    }
    if (t == 1023) g_rowptr[N_NODES] = incl;
}

__global__ void scatter_kernel(const int* __restrict__ rows,
                               const int* __restrict__ cols,
                               const float* __restrict__ vals, int E) {
    int i = blockIdx.x * blockDim.x + threadIdx.x;
    if (i < E) {
        int p = atomicAdd(&g_ofs[rows[i]], 1);
        g_scols[p] = cols[i];
        g_svals[p] = vals[i];
    }
}

// ---------------- weight convert fp32 -> fp16 (layouts already [k][n]) -------
__global__ void cvt_weights(const float* __restrict__ W1,
                            const float* __restrict__ W2,
                            const float* __restrict__ Wf) {
    const int i = blockIdx.x * blockDim.x + threadIdx.x;
    constexpr int S1 = KDIM * H_DIM;          // 65536
    constexpr int S2 = 2 * S1;                // 131072
    constexpr int S3 = S2 + KDIM * L_DIM;     // 163840
    if (i < S1)      g_W1h[i]      = __float2half_rn(W1[i]);
    else if (i < S2) g_W2h[i - S1] = __float2half_rn(W2[i - S1]);
    else if (i < S3) g_Wfh[i - S2] = __float2half_rn(Wf[i - S2]);
}

// ---------------- SpMM (half gather, fp32 out) + fused BN stats --------------
__device__ __forceinline__ void accum8(float* acc, uint4 u, float v) {
    const __half2* h = reinterpret_cast<const __half2*>(&u);
    #pragma unroll
    for (int j = 0; j < 4; j++) {
        float2 f = __half22float2(h[j]);
        acc[2 * j]     += v * f.x;
        acc[2 * j + 1] += v * f.y;
    }
}

__global__ __launch_bounds__(256)
void spmm_stats_kernel(const __half* __restrict__ x, float* __restrict__ y) {
    __shared__ float ss[8][H_DIM];
    __shared__ float sq[8][H_DIM];
    const int tid  = threadIdx.x;
    const int wid  = tid >> 5;
    const int lane = tid & 31;
    float s[8] = {}, q[8] = {};

    for (int r = 0; r < 4; r++) {
        const int row = blockIdx.x * 32 + wid * 4 + r;
        if (row < N_NODES) {
            int p = g_rowptr[row];
            const int e = g_rowptr[row + 1];
            float acc[8] = {};
            for (; p + 2 <= e; p += 2) {
                const int   c0 = __ldg(&g_scols[p]),     c1 = __ldg(&g_scols[p + 1]);
                const float v0 = __ldg(&g_svals[p]),     v1 = __ldg(&g_svals[p + 1]);
                uint4 u0 = __ldg(reinterpret_cast<const uint4*>(x + (size_t)c0 * H_DIM) + lane);
                uint4 u1 = __ldg(reinterpret_cast<const uint4*>(x + (size_t)c1 * H_DIM) + lane);
                accum8(acc, u0, v0);
                accum8(acc, u1, v1);
            }
            if (p < e) {
                const int   c0 = __ldg(&g_scols[p]);
                const float v0 = __ldg(&g_svals[p]);
                uint4 u0 = __ldg(reinterpret_cast<const uint4*>(x + (size_t)c0 * H_DIM) + lane);
                accum8(acc, u0, v0);
            }
            float4* yp = reinterpret_cast<float4*>(y + (size_t)row * H_DIM + lane * 8);
            yp[0] = make_float4(acc[0], acc[1], acc[2], acc[3]);
            yp[1] = make_float4(acc[4], acc[5], acc[6], acc[7]);
            #pragma unroll
            for (int j = 0; j < 8; j++) { s[j] += acc[j]; q[j] += acc[j] * acc[j]; }
        }
    }

    #pragma unroll
    for (int j = 0; j < 8; j++) {
        ss[wid][lane * 8 + j] = s[j];
        sq[wid][lane * 8 + j] = q[j];
    }
    __syncthreads();
    const int ch = tid;
    float S = 0.f, Q = 0.f;
    #pragma unroll
    for (int w = 0; w < 8; w++) { S += ss[w][ch]; Q += sq[w][ch]; }
    atomicAdd(&g_stats[ch], (double)S);
    atomicAdd(&g_stats[H_DIM + ch], (double)Q);
}

__global__ void bn_final_kernel(const float* __restrict__ gamma,
                                const float* __restrict__ beta,
                                float* __restrict__ oa, float* __restrict__ oc, int M) {
    const int t = threadIdx.x;
    double s = g_stats[t], sq = g_stats[H_DIM + t];
    float mean = (float)(s / M);
    float var  = (float)(sq / M) - mean * mean;
    float rstd = rsqrtf(var + EPS_BN);
    float a = gamma[t] * rstd;
    oa[t] = a;
    oc[t] = beta[t] - mean * a;
}

// ---------------- fp16 tensor-core GEMM --------------------------------------
// C[M, GN-slice] = op(A fp32)[M, 256] @ Bh[256, GN]
//   FUSE_BN: A col k -> relu(x*bna[k]+bnc[k]) before half convert
//   GATHER : A row m read from A[gidx[m]]
// Block tile 128x128, BK=32, 256 thr = 8 warps (2m x 4n), warp tile 64x32.
// A smem: row-major [m][k] halves, row stride 80B (pad -> conflict-free ldmatrix).
// B smem: row-major [k][n] halves, 256B rows, 16B-chunk XOR swizzle (c ^= k&7).
template<int GN, bool FUSE_BN, bool GATHER, bool BIAS, bool OUT_HALF>
__global__ __launch_bounds__(256, 2)
void hgemm(const float* __restrict__ A, const __half* __restrict__ Bh,
           const float* __restrict__ bias, void* __restrict__ Cptr,
           int M, const int* __restrict__ gidx,
           const float* __restrict__ bna, const float* __restrict__ bnc) {
    constexpr int ASTR = 80;
    constexpr int ASZ  = 128 * ASTR;   // 10240 B per stage
    constexpr int BSZ  = 32 * 256;     // 8192 B per stage
    __shared__ __align__(16) char sAm[2 * ASZ];
    __shared__ __align__(16) char sBm[2 * BSZ];
    const uint32_t sAu = smem_u32(sAm);
    const uint32_t sBu = smem_u32(sBm);

    const int tid  = threadIdx.x;
    const int lane = tid & 31;
    const int wid  = tid >> 5;
    const int wm   = wid & 1;
    const int wn   = wid >> 1;
    const int g    = lane >> 2;
    const int t4   = lane & 3;
    const int lrow = lane & 15;
    const int lko  = (lane >> 4) << 4;       // 0 or 16 bytes
    const int row0 = blockIdx.y * 128;
    const int col0 = blockIdx.x * 128;

    const int am = tid >> 1;                 // A staging row 0..127
    const int ak = tid & 1;                  // which 16-k half of 32-k chunk

    float4 af[4];
    float acc[4][4][4];
    #pragma unroll
    for (int i = 0; i < 4; i++)
        #pragma unroll
        for (int j = 0; j < 4; j++)
            #pragma unroll
            for (int k = 0; k < 4; k++) acc[i][j][k] = 0.f;

    auto ldgA = [&](int c) {
        const int gm = row0 + am;
        const int k0 = c * 32 + ak * 16;
        if (gm < M) {
            const int src = GATHER ? __ldg(&gidx[gm]) : gm;
            const float4* p = reinterpret_cast<const float4*>(A + (size_t)src * KDIM + k0);
            af[0] = p[0]; af[1] = p[1]; af[2] = p[2]; af[3] = p[3];
        } else {
            af[0] = af[1] = af[2] = af[3] = make_float4(0.f, 0.f, 0.f, 0.f);
        }
    };

    auto stsA = [&](int c, int buf) {
        const int k0 = c * 32 + ak * 16;
        float v[16];
        *reinterpret_cast<float4*>(v)      = af[0];
        *reinterpret_cast<float4*>(v + 4)  = af[1];
        *reinterpret_cast<float4*>(v + 8)  = af[2];
        *reinterpret_cast<float4*>(v + 12) = af[3];
        if (FUSE_BN) {
            #pragma unroll
            for (int q2 = 0; q2 < 4; q2++) {
                float4 aa = *reinterpret_cast<const float4*>(bna + k0 + q2 * 4);
                float4 cc = *reinterpret_cast<const float4*>(bnc + k0 + q2 * 4);
                float* vp = v + q2 * 4;
                vp[0] = fmaxf(vp[0] * aa.x + cc.x, 0.f);
                vp[1] = fmaxf(vp[1] * aa.y + cc.y, 0.f);
                vp[2] = fmaxf(vp[2] * aa.z + cc.z, 0.f);
                vp[3] = fmaxf(vp[3] * aa.w + cc.w, 0.f);
            }
        }
        uint32_t h[8];
        #pragma unroll
        for (int j = 0; j < 8; j++) h[j] = pack_h2(v[2 * j], v[2 * j + 1]);
        char* dst = sAm + buf * ASZ + am * ASTR + ak * 32;
        *reinterpret_cast<uint4*>(dst)      = make_uint4(h[0], h[1], h[2], h[3]);
        *reinterpret_cast<uint4*>(dst + 16) = make_uint4(h[4], h[5], h[6], h[7]);
    };

    auto stageB = [&](int c, int buf) {
        const uint32_t base = sBu + buf * BSZ;
        const __half* src = Bh + (size_t)(c * 32) * GN + col0;
        #pragma unroll
        for (int i = 0; i < 2; i++) {
            const int id = tid + i * 256;
            const int kk = id >> 4, cc = id & 15;
            const uint32_t dst = base + kk * 256 + ((cc ^ (kk & 7)) << 4);
            const void* gp = src + (size_t)kk * GN + cc * 8;
            asm volatile("cp.async.ca.shared.global [%0], [%1], 16;\n"
                         :: "r"(dst), "l"(gp));
        }
        asm volatile("cp.async.commit_group;\n" ::: "memory");
    };

    auto compute = [&](int buf) {
        const uint32_t aB = sAu + buf * ASZ;
        const uint32_t bB = sBu + buf * BSZ;
        #pragma unroll
        for (int kb = 0; kb < 32; kb += 16) {
            uint32_t a[4][4];
            #pragma unroll
            for (int mf = 0; mf < 4; mf++) {
                const int m0 = wm * 64 + mf * 16;
                const uint32_t ad = aB + (uint32_t)(m0 + lrow) * ASTR + kb * 2 + lko;
                asm volatile("ldmatrix.sync.aligned.m8n8.x4.shared.b16 {%0,%1,%2,%3}, [%4];"
                             : "=r"(a[mf][0]), "=r"(a[mf][1]), "=r"(a[mf][2]), "=r"(a[mf][3])
                             : "r"(ad));
            }
            uint32_t b[4][2];
            #pragma unroll
            for (int pr = 0; pr < 2; pr++) {
                const int n0 = wn * 32 + pr * 16;
                const int rk = kb + lrow;
                const int ch = (n0 >> 3) + (lane >> 4);
                const uint32_t bd = bB + (uint32_t)rk * 256 + ((ch ^ (rk & 7)) << 4);
                uint32_t r0, r1, r2, r3;
                asm volatile("ldmatrix.sync.aligned.m8n8.x4.trans.shared.b16 {%0,%1,%2,%3}, [%4];"
                             : "=r"(r0), "=r"(r1), "=r"(r2), "=r"(r3) : "r"(bd));
                b[pr * 2][0] = r0; b[pr * 2][1] = r1;
                b[pr * 2 + 1][0] = r2; b[pr * 2 + 1][1] = r3;
            }
            #pragma unroll
            for (int mf = 0; mf < 4; mf++)
                #pragma unroll
                for (int nf = 0; nf < 4; nf++)
                    asm volatile(
                        "mma.sync.aligned.m16n8k16.row.col.f32.f16.f16.f32 "
                        "{%0,%1,%2,%3}, {%4,%5,%6,%7}, {%8,%9}, {%0,%1,%2,%3};"
                        : "+f"(acc[mf][nf][0]), "+f"(acc[mf][nf][1]),
                          "+f"(acc[mf][nf][2]), "+f"(acc[mf][nf][3])
                        : "r"(a[mf][0]), "r"(a[mf][1]), "r"(a[mf][2]), "r"(a[mf][3]),
                          "r"(b[nf][0]), "r"(b[nf][1]));
        }
    };

    constexpr int NCH = KDIM / 32;   // 8 chunks
    stageB(0, 0);
    ldgA(0);
    stsA(0, 0);
    ldgA(1);

    for (int c = 0; c < NCH; c++) {
        const int buf = c & 1;
        asm volatile("cp.async.wait_group 0;\n" ::: "memory");
        __syncthreads();
        if (c + 1 < NCH) stageB(c + 1, buf ^ 1);
        compute(buf);
        if (c + 1 < NCH) {
            stsA(c + 1, buf ^ 1);
            if (c + 2 < NCH) ldgA(c + 2);
        }
    }

    // ---- epilogue ----
    #pragma unroll
    for (int mf = 0; mf < 4; mf++) {
        const int r = row0 + wm * 64 + mf * 16 + g;
        #pragma unroll
        for (int nf = 0; nf < 4; nf++) {
            const int cb = col0 + wn * 32 + nf * 8 + t4 * 2;
            float b0 = 0.f, b1 = 0.f;
            if (BIAS) { b0 = __ldg(&bias[cb]); b1 = __ldg(&bias[cb + 1]); }
            if (OUT_HALF) {
                __half* C = (__half*)Cptr;
                if (r < M) {
                    uint32_t h = pack_h2(acc[mf][nf][0] + b0, acc[mf][nf][1] + b1);
                    *reinterpret_cast<uint32_t*>(C + (size_t)r * GN + cb) = h;
                }
                if (r + 8 < M) {
                    uint32_t h = pack_h2(acc[mf][nf][2] + b0, acc[mf][nf][3] + b1);
                    *reinterpret_cast<uint32_t*>(C + (size_t)(r + 8) * GN + cb) = h;
                }
            } else {
                float* C = (float*)Cptr;
                if (r < M)
                    *reinterpret_cast<float2*>(C + (size_t)r * GN + cb) =
                        make_float2(acc[mf][nf][0] + b0, acc[mf][nf][1] + b1);
                if (r + 8 < M)
                    *reinterpret_cast<float2*>(C + (size_t)(r + 8) * GN + cb) =
                        make_float2(acc[mf][nf][2] + b0, acc[mf][nf][3] + b1);
            }
        }
    }
}

// ---------------- launch -----------------------------------------------------
extern "C" void kernel_launch(void* const* d_in, const int* in_sizes, int n_in,
                              void* d_out, int out_size) {
    const float* features  = (const float*)d_in[0];
    const float* edge_vals = (const float*)d_in[1];
    const float* W1        = (const float*)d_in[2];
    const float* db1       = (const float*)d_in[3];
    // d_in[4] = b1  (cancels inside BatchNorm, skipped)
    const float* g1        = (const float*)d_in[5];
    const float* be1       = (const float*)d_in[6];
    const float* W2        = (const float*)d_in[7];
    // d_in[8] = b2  (cancels inside BatchNorm, skipped)
    const float* g2        = (const float*)d_in[9];
    const float* be2       = (const float*)d_in[10];
    const float* Wf        = (const float*)d_in[11];
    const float* bf        = (const float*)d_in[12];
    const int*   edge_rows = (const int*)d_in[13];
    const int*   edge_cols = (const int*)d_in[14];
    const int*   idx       = (const int*)d_in[15];

    const int E  = in_sizes[1];
    const int Mi = in_sizes[15];
    float* out = (float*)d_out;

    __half *hH, *w1h, *w2h, *wfh;
    float *yF, *a1, *c1, *a2, *c2;
    int* cnt; double* stats;
    cudaGetSymbolAddress((void**)&hH,  g_hH);
    cudaGetSymbolAddress((void**)&yF,  g_yF);
    cudaGetSymbolAddress((void**)&w1h, g_W1h);
    cudaGetSymbolAddress((void**)&w2h, g_W2h);
    cudaGetSymbolAddress((void**)&wfh, g_Wfh);
    cudaGetSymbolAddress((void**)&cnt, g_cnt);
    cudaGetSymbolAddress((void**)&stats, g_stats);
    cudaGetSymbolAddress((void**)&a1, g_a1);
    cudaGetSymbolAddress((void**)&c1, g_c1);
    cudaGetSymbolAddress((void**)&a2, g_a2);
    cudaGetSymbolAddress((void**)&c2, g_c2);

    // --- CSR build ---
    cudaMemsetAsync(cnt, 0, (N_NODES + 1) * sizeof(int), 0);
    hist_kernel<<<(E + 255) / 256, 256>>>(edge_rows, E);
    scan_kernel<<<1, 1024>>>();
    scatter_kernel<<<(E + 255) / 256, 256>>>(edge_rows, edge_cols, edge_vals, E);

    // --- weights -> fp16 ---
    cvt_weights<<<(2 * KDIM * H_DIM + KDIM * L_DIM + 255) / 256, 256>>>(W1, W2, Wf);

    const dim3 gmain(H_DIM / 128, (N_NODES + 127) / 128);   // (2, 391)
    const int  spmm_blocks = (N_NODES + 31) / 32;

    // --- layer 1: hH = half(features @ W1 + db1) ---
    hgemm<256, false, false, true, true><<<gmain, 256>>>(
        features, w1h, db1, hH, N_NODES, nullptr, nullptr, nullptr);
    cudaMemsetAsync(stats, 0, 2 * H_DIM * sizeof(double), 0);
    spmm_stats_kernel<<<spmm_blocks, 256>>>(hH, yF);
    bn_final_kernel<<<1, H_DIM>>>(g1, be1, a1, c1, N_NODES);

    // --- layer 2: hH = half(relu(bn1(yF)) @ W2) ---
    hgemm<256, true, false, false, true><<<gmain, 256>>>(
        yF, w2h, nullptr, hH, N_NODES, nullptr, a1, c1);
    cudaMemsetAsync(stats, 0, 2 * H_DIM * sizeof(double), 0);
    spmm_stats_kernel<<<spmm_blocks, 256>>>(hH, yF);
    bn_final_kernel<<<1, H_DIM>>>(g2, be2, a2, c2, N_NODES);

    // --- head: out = relu(bn2(yF))[idx] @ Wf + bf  (fp32 out) ---
    const dim3 ghead(1, (Mi + 127) / 128);
    hgemm<128, true, true, true, false><<<ghead, 256>>>(
        yF, wfh, bf, out, Mi, idx, a2, c2);
}

// round 11
// speedup vs baseline: 2.5953x; 1.0618x over previous
#include <cuda_runtime.h>
#include <cuda_fp16.h>
#include <cstdint>

#define N_NODES 50000
#define N_EDGES 800000
#define KDIM    256
#define H_DIM   256
#define L_DIM   128
#define EPS_BN  1e-5f

// ---------------- scratch (device globals; no allocations allowed) ----------
__device__ __align__(16) __half g_hH[(size_t)N_NODES * H_DIM];   // GEMM half outputs
__device__ __align__(16) __half g_yH[(size_t)N_NODES * H_DIM];   // SpMM half outputs
__device__ __align__(16) __half g_W1h[KDIM * H_DIM];
__device__ __align__(16) __half g_W2h[KDIM * H_DIM];
__device__ __align__(16) __half g_Wfh[KDIM * L_DIM];
__device__ int      g_cnt[N_NODES + 1];
__device__ int      g_rowptr[N_NODES + 1];
__device__ int      g_ofs[N_NODES];
__device__ int      g_scols[N_EDGES];
__device__ float    g_svals[N_EDGES];
__device__ double   g_stats[2][2 * H_DIM];       // per-layer [sum | sumsq]
__device__ unsigned g_done[2];                   // per-layer finalize counters
__device__ __align__(16) float g_a1[H_DIM];
__device__ __align__(16) float g_c1[H_DIM];
__device__ __align__(16) float g_a2[H_DIM];
__device__ __align__(16) float g_c2[H_DIM];

// ---------------- helpers ----------------------------------------------------
__device__ __forceinline__ uint32_t smem_u32(const void* p) {
    uint32_t a;
    asm("{ .reg .u64 t; cvta.to.shared.u64 t, %1; cvt.u32.u64 %0, t; }"
        : "=r"(a) : "l"(p));
    return a;
}

__device__ __forceinline__ uint32_t pack_h2(float a, float b) {
    __half2 h = __floats2half2_rn(a, b);
    return *reinterpret_cast<uint32_t*>(&h);
}

// ---------------- CSR build --------------------------------------------------
__global__ void hist_kernel(const int* __restrict__ rows, int E) {
    int i = blockIdx.x * blockDim.x + threadIdx.x;
    if (i < E) atomicAdd(&g_cnt[rows[i]], 1);
}

__global__ void scan_kernel() {
    __shared__ int part[1024];
    const int t = threadIdx.x;
    const int CH = (N_NODES + 1023) / 1024;
    const int base = t * CH;
    int local = 0;
    for (int i = 0; i < CH; i++) {
        int r = base + i;
        if (r < N_NODES) local += g_cnt[r];
    }
    part[t] = local;
    __syncthreads();
    for (int off = 1; off < 1024; off <<= 1) {
        int v = (t >= off) ? part[t - off] : 0;
        __syncthreads();
        part[t] += v;
        __syncthreads();
    }
    int incl = part[t];
    int run = incl - local;
    for (int i = 0; i < CH; i++) {
        int r = base + i;
        if (r < N_NODES) {
            g_rowptr[r] = run;
            g_ofs[r]    = run;
            run += g_cnt[r];
        }
    }
    if (t == 1023) g_rowptr[N_NODES] = incl;
}

__global__ void scatter_kernel(const int* __restrict__ rows,
                               const int* __restrict__ cols,
                               const float* __restrict__ vals, int E) {
    int i = blockIdx.x * blockDim.x + threadIdx.x;
    if (i < E) {
        int p = atomicAdd(&g_ofs[rows[i]], 1);
        g_scols[p] = cols[i];
        g_svals[p] = vals[i];
    }
}

// ---------------- weight convert fp32 -> fp16 (layouts already [k][n]) -------
__global__ void cvt_weights(const float* __restrict__ W1,
                            const float* __restrict__ W2,
                            const float* __restrict__ Wf) {
    const int i = blockIdx.x * blockDim.x + threadIdx.x;
    constexpr int S1 = KDIM * H_DIM;
    constexpr int S2 = 2 * S1;
    constexpr int S3 = S2 + KDIM * L_DIM;
    if (i < S1)      g_W1h[i]      = __float2half_rn(W1[i]);
    else if (i < S2) g_W2h[i - S1] = __float2half_rn(W2[i - S1]);
    else if (i < S3) g_Wfh[i - S2] = __float2half_rn(Wf[i - S2]);
}

// ---------------- SpMM (half gather, half out) + fused BN stats + finalize ---
__device__ __forceinline__ void accum8(float* acc, uint4 u, float v) {
    const __half2* h = reinterpret_cast<const __half2*>(&u);
    #pragma unroll
    for (int j = 0; j < 4; j++) {
        float2 f = __half22float2(h[j]);
        acc[2 * j]     += v * f.x;
        acc[2 * j + 1] += v * f.y;
    }
}

template<int LAYER>
__global__ __launch_bounds__(256)
void spmm_stats_kernel(const __half* __restrict__ x, __half* __restrict__ y,
                       const float* __restrict__ gamma, const float* __restrict__ beta,
                       float* __restrict__ oa, float* __restrict__ oc) {
    __shared__ float ss[8][H_DIM];
    __shared__ float sq[8][H_DIM];
    const int tid  = threadIdx.x;
    const int wid  = tid >> 5;
    const int lane = tid & 31;
    float s[8] = {}, q[8] = {};

    for (int r = 0; r < 4; r++) {
        const int row = blockIdx.x * 32 + wid * 4 + r;
        if (row < N_NODES) {
            int p = g_rowptr[row];
            const int e = g_rowptr[row + 1];
            float acc[8] = {};
            for (; p + 2 <= e; p += 2) {
                const int   c0 = __ldg(&g_scols[p]),     c1 = __ldg(&g_scols[p + 1]);
                const float v0 = __ldg(&g_svals[p]),     v1 = __ldg(&g_svals[p + 1]);
                uint4 u0 = __ldg(reinterpret_cast<const uint4*>(x + (size_t)c0 * H_DIM) + lane);
                uint4 u1 = __ldg(reinterpret_cast<const uint4*>(x + (size_t)c1 * H_DIM) + lane);
                accum8(acc, u0, v0);
                accum8(acc, u1, v1);
            }
            if (p < e) {
                const int   c0 = __ldg(&g_scols[p]);
                const float v0 = __ldg(&g_svals[p]);
                uint4 u0 = __ldg(reinterpret_cast<const uint4*>(x + (size_t)c0 * H_DIM) + lane);
                accum8(acc, u0, v0);
            }
            uint4 o;
            __half2* oh = reinterpret_cast<__half2*>(&o);
            oh[0] = __floats2half2_rn(acc[0], acc[1]);
            oh[1] = __floats2half2_rn(acc[2], acc[3]);
            oh[2] = __floats2half2_rn(acc[4], acc[5]);
            oh[3] = __floats2half2_rn(acc[6], acc[7]);
            *reinterpret_cast<uint4*>(y + (size_t)row * H_DIM + lane * 8) = o;
            #pragma unroll
            for (int j = 0; j < 8; j++) { s[j] += acc[j]; q[j] += acc[j] * acc[j]; }
        }
    }

    #pragma unroll
    for (int j = 0; j < 8; j++) {
        ss[wid][lane * 8 + j] = s[j];
        sq[wid][lane * 8 + j] = q[j];
    }
    __syncthreads();
    const int ch = tid;
    float S = 0.f, Q = 0.f;
    #pragma unroll
    for (int w = 0; w < 8; w++) { S += ss[w][ch]; Q += sq[w][ch]; }
    double* st = g_stats[LAYER];
    atomicAdd(&st[ch], (double)S);
    atomicAdd(&st[H_DIM + ch], (double)Q);

    // ---- last-block finalize: compute per-channel a, c ----
    __shared__ unsigned s_last;
    __threadfence();
    if (tid == 0) s_last = (atomicAdd(&g_done[LAYER], 1u) == gridDim.x - 1u) ? 1u : 0u;
    __syncthreads();
    if (s_last) {
        __threadfence();
        double sv = *((volatile double*)&st[ch]);
        double qv = *((volatile double*)&st[H_DIM + ch]);
        float mean = (float)(sv / N_NODES);
        float var  = (float)(qv / N_NODES) - mean * mean;
        float rstd = rsqrtf(var + EPS_BN);
        float a = gamma[ch] * rstd;
        oa[ch] = a;
        oc[ch] = beta[ch] - mean * a;
    }
}

// ---------------- fp16 tensor-core GEMM --------------------------------------
// C[M, GN] = op(A)[M, 256] @ Bh[256, GN];  A is fp32 or fp16 (template AT)
//   FUSE_BN: A col k -> relu(x*bna[k]+bnc[k]) before half convert
//   GATHER : A row m read from A[gidx[m]]
template<int GN, bool FUSE_BN, bool GATHER, bool BIAS, bool OUT_HALF, typename AT>
__global__ __launch_bounds__(256, 2)
void hgemm(const AT* __restrict__ A, const __half* __restrict__ Bh,
           const float* __restrict__ bias, void* __restrict__ Cptr,
           int M, const int* __restrict__ gidx,
           const float* __restrict__ bna, const float* __restrict__ bnc) {
    constexpr int ASTR = 80;
    constexpr int ASZ  = 128 * ASTR;
    constexpr int BSZ  = 32 * 256;
    __shared__ __align__(16) char sAm[2 * ASZ];
    __shared__ __align__(16) char sBm[2 * BSZ];
    const uint32_t sAu = smem_u32(sAm);
    const uint32_t sBu = smem_u32(sBm);

    const int tid  = threadIdx.x;
    const int lane = tid & 31;
    const int wid  = tid >> 5;
    const int wm   = wid & 1;
    const int wn   = wid >> 1;
    const int g    = lane >> 2;
    const int t4   = lane & 3;
    const int lrow = lane & 15;
    const int lko  = (lane >> 4) << 4;
    const int row0 = blockIdx.y * 128;
    const int col0 = blockIdx.x * 128;

    const int am = tid >> 1;                 // A staging row 0..127
    const int ak = tid & 1;                  // which 16-k half of 32-k chunk

    float4 af[4];                            // fp32 A raw (float path)
    uint4  ah[2];                            // fp16 A raw (half path)
    float acc[4][4][4];
    #pragma unroll
    for (int i = 0; i < 4; i++)
        #pragma unroll
        for (int j = 0; j < 4; j++)
            #pragma unroll
            for (int k = 0; k < 4; k++) acc[i][j][k] = 0.f;

    auto ldgA = [&](int c) {
        const int gm = row0 + am;
        const int k0 = c * 32 + ak * 16;
        if (gm < M) {
            const int src = GATHER ? __ldg(&gidx[gm]) : gm;
            if constexpr (sizeof(AT) == 4) {
                const float4* p = reinterpret_cast<const float4*>(
                    (const float*)A + (size_t)src * KDIM + k0);
                af[0] = p[0]; af[1] = p[1]; af[2] = p[2]; af[3] = p[3];
            } else {
                const uint4* p = reinterpret_cast<const uint4*>(
                    (const __half*)A + (size_t)src * KDIM + k0);
                ah[0] = p[0]; ah[1] = p[1];
            }
        } else {
            if constexpr (sizeof(AT) == 4) {
                af[0] = af[1] = af[2] = af[3] = make_float4(0.f, 0.f, 0.f, 0.f);
            } else {
                ah[0] = ah[1] = make_uint4(0u, 0u, 0u, 0u);
            }
        }
    };

    auto stsA = [&](int c, int buf) {
        const int k0 = c * 32 + ak * 16;
        float v[16];
        if constexpr (sizeof(AT) == 4) {
            *reinterpret_cast<float4*>(v)      = af[0];
            *reinterpret_cast<float4*>(v + 4)  = af[1];
            *reinterpret_cast<float4*>(v + 8)  = af[2];
            *reinterpret_cast<float4*>(v + 12) = af[3];
        } else {
            const __half2* hp = reinterpret_cast<const __half2*>(ah);
            #pragma unroll
            for (int j = 0; j < 8; j++) {
                float2 f = __half22float2(hp[j]);
                v[2 * j] = f.x; v[2 * j + 1] = f.y;
            }
        }
        if (FUSE_BN) {
            #pragma unroll
            for (int q2 = 0; q2 < 4; q2++) {
                float4 aa = *reinterpret_cast<const float4*>(bna + k0 + q2 * 4);
                float4 cc = *reinterpret_cast<const float4*>(bnc + k0 + q2 * 4);
                float* vp = v + q2 * 4;
                vp[0] = fmaxf(vp[0] * aa.x + cc.x, 0.f);
                vp[1] = fmaxf(vp[1] * aa.y + cc.y, 0.f);
                vp[2] = fmaxf(vp[2] * aa.z + cc.z, 0.f);
                vp[3] = fmaxf(vp[3] * aa.w + cc.w, 0.f);
            }
        }
        uint32_t h[8];
        #pragma unroll
        for (int j = 0; j < 8; j++) h[j] = pack_h2(v[2 * j], v[2 * j + 1]);
        char* dst = sAm + buf * ASZ + am * ASTR + ak * 32;
        *reinterpret_cast<uint4*>(dst)      = make_uint4(h[0], h[1], h[2], h[3]);
        *reinterpret_cast<uint4*>(dst + 16) = make_uint4(h[4], h[5], h[6], h[7]);
    };

    auto stageB = [&](int c, int buf) {
        const uint32_t base = sBu + buf * BSZ;
        const __half* src = Bh + (size_t)(c * 32) * GN + col0;
        #pragma unroll
        for (int i = 0; i < 2; i++) {
            const int id = tid + i * 256;
            const int kk = id >> 4, cc = id & 15;
            const uint32_t dst = base + kk * 256 + ((cc ^ (kk & 7)) << 4);
            const void* gp = src + (size_t)kk * GN + cc * 8;
            asm volatile("cp.async.ca.shared.global [%0], [%1], 16;\n"
                         :: "r"(dst), "l"(gp));
        }
        asm volatile("cp.async.commit_group;\n" ::: "memory");
    };

    auto compute = [&](int buf) {
        const uint32_t aB = sAu + buf * ASZ;
        const uint32_t bB = sBu + buf * BSZ;
        #pragma unroll
        for (int kb = 0; kb < 32; kb += 16) {
            uint32_t a[4][4];
            #pragma unroll
            for (int mf = 0; mf < 4; mf++) {
                const int m0 = wm * 64 + mf * 16;
                const uint32_t ad = aB + (uint32_t)(m0 + lrow) * ASTR + kb * 2 + lko;
                asm volatile("ldmatrix.sync.aligned.m8n8.x4.shared.b16 {%0,%1,%2,%3}, [%4];"
                             : "=r"(a[mf][0]), "=r"(a[mf][1]), "=r"(a[mf][2]), "=r"(a[mf][3])
                             : "r"(ad));
            }
            uint32_t b[4][2];
            #pragma unroll
            for (int pr = 0; pr < 2; pr++) {
                const int n0 = wn * 32 + pr * 16;
                const int rk = kb + lrow;
                const int ch = (n0 >> 3) + (lane >> 4);
                const uint32_t bd = bB + (uint32_t)rk * 256 + ((ch ^ (rk & 7)) << 4);
                uint32_t r0, r1, r2, r3;
                asm volatile("ldmatrix.sync.aligned.m8n8.x4.trans.shared.b16 {%0,%1,%2,%3}, [%4];"
                             : "=r"(r0), "=r"(r1), "=r"(r2), "=r"(r3) : "r"(bd));
                b[pr * 2][0] = r0; b[pr * 2][1] = r1;
                b[pr * 2 + 1][0] = r2; b[pr * 2 + 1][1] = r3;
            }
            #pragma unroll
            for (int mf = 0; mf < 4; mf++)
                #pragma unroll
                for (int nf = 0; nf < 4; nf++)
                    asm volatile(
                        "mma.sync.aligned.m16n8k16.row.col.f32.f16.f16.f32 "
                        "{%0,%1,%2,%3}, {%4,%5,%6,%7}, {%8,%9}, {%0,%1,%2,%3};"
                        : "+f"(acc[mf][nf][0]), "+f"(acc[mf][nf][1]),
                          "+f"(acc[mf][nf][2]), "+f"(acc[mf][nf][3])
                        : "r"(a[mf][0]), "r"(a[mf][1]), "r"(a[mf][2]), "r"(a[mf][3]),
                          "r"(b[nf][0]), "r"(b[nf][1]));
        }
    };

    constexpr int NCH = KDIM / 32;   // 8 chunks
    stageB(0, 0);
    ldgA(0);
    stsA(0, 0);
    ldgA(1);

    for (int c = 0; c < NCH; c++) {
        const int buf = c & 1;
        asm volatile("cp.async.wait_group 0;\n" ::: "memory");
        __syncthreads();
        if (c + 1 < NCH) stageB(c + 1, buf ^ 1);
        compute(buf);
        if (c + 1 < NCH) {
            stsA(c + 1, buf ^ 1);
            if (c + 2 < NCH) ldgA(c + 2);
        }
    }

    // ---- epilogue ----
    #pragma unroll
    for (int mf = 0; mf < 4; mf++) {
        const int r = row0 + wm * 64 + mf * 16 + g;
        #pragma unroll
        for (int nf = 0; nf < 4; nf++) {
            const int cb = col0 + wn * 32 + nf * 8 + t4 * 2;
            float b0 = 0.f, b1 = 0.f;
            if (BIAS) { b0 = __ldg(&bias[cb]); b1 = __ldg(&bias[cb + 1]); }
            if (OUT_HALF) {
                __half* C = (__half*)Cptr;
                if (r < M) {
                    uint32_t h = pack_h2(acc[mf][nf][0] + b0, acc[mf][nf][1] + b1);
                    *reinterpret_cast<uint32_t*>(C + (size_t)r * GN + cb) = h;
                }
                if (r + 8 < M) {
                    uint32_t h = pack_h2(acc[mf][nf][2] + b0, acc[mf][nf][3] + b1);
                    *reinterpret_cast<uint32_t*>(C + (size_t)(r + 8) * GN + cb) = h;
                }
            } else {
                float* C = (float*)Cptr;
                if (r < M)
                    *reinterpret_cast<float2*>(C + (size_t)r * GN + cb) =
                        make_float2(acc[mf][nf][0] + b0, acc[mf][nf][1] + b1);
                if (r + 8 < M)
                    *reinterpret_cast<float2*>(C + (size_t)(r + 8) * GN + cb) =
                        make_float2(acc[mf][nf][2] + b0, acc[mf][nf][3] + b1);
            }
        }
    }
}

// ---------------- launch -----------------------------------------------------
extern "C" void kernel_launch(void* const* d_in, const int* in_sizes, int n_in,
                              void* d_out, int out_size) {
    const float* features  = (const float*)d_in[0];
    const float* edge_vals = (const float*)d_in[1];
    const float* W1        = (const float*)d_in[2];
    const float* db1       = (const float*)d_in[3];
    // d_in[4] = b1  (cancels inside BatchNorm, skipped)
    const float* g1        = (const float*)d_in[5];
    const float* be1       = (const float*)d_in[6];
    const float* W2        = (const float*)d_in[7];
    // d_in[8] = b2  (cancels inside BatchNorm, skipped)
    const float* g2        = (const float*)d_in[9];
    const float* be2       = (const float*)d_in[10];
    const float* Wf        = (const float*)d_in[11];
    const float* bf        = (const float*)d_in[12];
    const int*   edge_rows = (const int*)d_in[13];
    const int*   edge_cols = (const int*)d_in[14];
    const int*   idx       = (const int*)d_in[15];

    const int E  = in_sizes[1];
    const int Mi = in_sizes[15];
    float* out = (float*)d_out;

    __half *hH, *yH, *w1h, *w2h, *wfh;
    float *a1, *c1, *a2, *c2;
    int* cnt; double* stats; unsigned* done;
    cudaGetSymbolAddress((void**)&hH,  g_hH);
    cudaGetSymbolAddress((void**)&yH,  g_yH);
    cudaGetSymbolAddress((void**)&w1h, g_W1h);
    cudaGetSymbolAddress((void**)&w2h, g_W2h);
    cudaGetSymbolAddress((void**)&wfh, g_Wfh);
    cudaGetSymbolAddress((void**)&cnt, g_cnt);
    cudaGetSymbolAddress((void**)&stats, g_stats);
    cudaGetSymbolAddress((void**)&done, g_done);
    cudaGetSymbolAddress((void**)&a1, g_a1);
    cudaGetSymbolAddress((void**)&c1, g_c1);
    cudaGetSymbolAddress((void**)&a2, g_a2);
    cudaGetSymbolAddress((void**)&c2, g_c2);

    // ---- fork a second stream for the CSR build (independent of GEMM1) ----
    cudaStream_t s2 = 0;
    cudaEvent_t eFork = nullptr, eJoin = nullptr;
    bool forked = (cudaStreamCreateWithFlags(&s2, cudaStreamNonBlocking) == cudaSuccess) &&
                  (cudaEventCreateWithFlags(&eFork, cudaEventDisableTiming) == cudaSuccess) &&
                  (cudaEventCreateWithFlags(&eJoin, cudaEventDisableTiming) == cudaSuccess);
    cudaStream_t sb = forked ? s2 : 0;

    if (forked) {
        cudaEventRecord(eFork, 0);
        cudaStreamWaitEvent(s2, eFork, 0);
    }

    // --- CSR build + stats/counter zeroing (forked stream) ---
    cudaMemsetAsync(cnt, 0, (N_NODES + 1) * sizeof(int), sb);
    cudaMemsetAsync(stats, 0, 2 * 2 * H_DIM * sizeof(double), sb);
    cudaMemsetAsync(done, 0, 2 * sizeof(unsigned), sb);
    hist_kernel<<<(E + 255) / 256, 256, 0, sb>>>(edge_rows, E);
    scan_kernel<<<1, 1024, 0, sb>>>();
    scatter_kernel<<<(E + 255) / 256, 256, 0, sb>>>(edge_rows, edge_cols, edge_vals, E);

    // --- main stream: weights + GEMM1 (overlaps CSR build) ---
    cvt_weights<<<(2 * KDIM * H_DIM + KDIM * L_DIM + 255) / 256, 256>>>(W1, W2, Wf);

    const dim3 gmain(H_DIM / 128, (N_NODES + 127) / 128);
    const int  spmm_blocks = (N_NODES + 31) / 32;

    hgemm<256, false, false, true, true, float><<<gmain, 256>>>(
        features, w1h, db1, hH, N_NODES, nullptr, nullptr, nullptr);

    if (forked) {
        cudaEventRecord(eJoin, s2);
        cudaStreamWaitEvent(0, eJoin, 0);
    }

    // --- layer 1 aggregate: yH = A@hH  (+BN stats, fused finalize -> a1,c1) ---
    spmm_stats_kernel<0><<<spmm_blocks, 256>>>(hH, yH, g1, be1, a1, c1);

    // --- layer 2: hH = half(relu(bn1(yH)) @ W2) ---
    hgemm<256, true, false, false, true, __half><<<gmain, 256>>>(
        yH, w2h, nullptr, hH, N_NODES, nullptr, a1, c1);
    spmm_stats_kernel<1><<<spmm_blocks, 256>>>(hH, yH, g2, be2, a2, c2);

    // --- head: out = relu(bn2(yH))[idx] @ Wf + bf  (fp32 out) ---
    const dim3 ghead(1, (Mi + 127) / 128);
    hgemm<128, true, true, true, false, __half><<<ghead, 256>>>(
        yH, wfh, bf, out, Mi, idx, a2, c2);

    if (forked) {
        cudaStreamDestroy(s2);
        cudaEventDestroy(eFork);
        cudaEventDestroy(eJoin);
    }
}